// round 2
// baseline (speedup 1.0000x reference)
#include <cuda_runtime.h>

// Problem constants (fixed by the dataset)
#define NN 200000
#define EE 3200000

// ---------------- static device scratch (no allocations allowed) ----------------
__device__ int   g_deg[NN];        // out-degree (by src) for normalization
__device__ int   g_cnt[NN];        // in-degree (by dst) for CSR
__device__ float g_dinv[NN];       // deg^{-1/2} or 0
__device__ int   g_off[NN + 1];    // CSR row offsets (by dst)
__device__ int   g_cur[NN];        // scatter cursors
__device__ int   g_bsum[1024];     // scan block sums
__device__ int   g_is64;           // 1 if edge_index stored as int64
__device__ int2  g_csr[EE];        // packed (src, weight-as-int) per edge, grouped by dst
__device__ float g_h[NN * 32];     // feature buffers
__device__ float g_a[NN * 32];
__device__ float g_t[NN * 32];
__device__ float g_b[NN * 32];

__device__ __forceinline__ float* fbuf(int id) {
    switch (id) {
        case 0:  return g_h;
        case 1:  return g_a;
        case 2:  return g_t;
        default: return g_b;
    }
}

// read edge endpoint k (0..2e-1) honoring dtype flag
__device__ __forceinline__ int edge_at(const void* ei, int idx, int is64) {
    if (is64) return (int)((const long long*)ei)[idx];
    return ((const int*)ei)[idx];
}

// ---------------- setup kernels ----------------
__global__ void k_detect(const void* ei) {
    // int64 layout: high word of every nonneg small value is 0.
    // int32 layout: these words are random node ids, virtually never all zero.
    __shared__ int any;
    if (threadIdx.x == 0) any = 0;
    __syncthreads();
    const int* w = (const int*)ei;
    for (int i = threadIdx.x; i < 1024; i += blockDim.x)
        if (w[2 * i + 1] != 0) atomicOr(&any, 1);
    __syncthreads();
    if (threadIdx.x == 0) g_is64 = (any == 0) ? 1 : 0;
}

__global__ void k_zero(int n) {
    int i = blockIdx.x * blockDim.x + threadIdx.x;
    if (i < n) { g_deg[i] = 0; g_cnt[i] = 0; }
}

__global__ void k_count(const void* ei, int e) {
    int i = blockIdx.x * blockDim.x + threadIdx.x;
    if (i < e) {
        int is64 = g_is64;
        int s = edge_at(ei, i, is64);
        int d = edge_at(ei, e + i, is64);
        atomicAdd(&g_deg[s], 1);
        atomicAdd(&g_cnt[d], 1);
    }
}

__global__ void k_dinv(int n) {
    int i = blockIdx.x * blockDim.x + threadIdx.x;
    if (i < n) {
        int d = g_deg[i];
        g_dinv[i] = (d > 0) ? rsqrtf((float)d) : 0.f;
    }
}

// Exclusive scan of g_cnt -> g_off, 3 kernels, 1024-wide blocks
__global__ void k_scan1(int n) {
    __shared__ int sh[1024];
    int tid = threadIdx.x;
    int i = blockIdx.x * 1024 + tid;
    int v = (i < n) ? g_cnt[i] : 0;
    sh[tid] = v;
    __syncthreads();
    for (int d = 1; d < 1024; d <<= 1) {
        int t = (tid >= d) ? sh[tid - d] : 0;
        __syncthreads();
        sh[tid] += t;
        __syncthreads();
    }
    if (i < n) g_off[i] = sh[tid] - v;   // exclusive within block
    if (tid == 1023) g_bsum[blockIdx.x] = sh[1023];
}

__global__ void k_scan2(int nb, int n) {
    if (threadIdx.x == 0 && blockIdx.x == 0) {
        int a = 0;
        for (int b = 0; b < nb; b++) { int t = g_bsum[b]; g_bsum[b] = a; a += t; }
        g_off[n] = a;   // == E
    }
}

__global__ void k_scan3(int n) {
    int i = blockIdx.x * blockDim.x + threadIdx.x;
    if (i < n) {
        int o = g_off[i] + g_bsum[i >> 10];
        g_off[i] = o;
        g_cur[i] = o;
    }
}

__global__ void k_scatter(const void* ei, int e) {
    int i = blockIdx.x * blockDim.x + threadIdx.x;
    if (i < e) {
        int is64 = g_is64;
        int s = edge_at(ei, i, is64);
        int d = edge_at(ei, e + i, is64);
        float w = -g_dinv[s] * g_dinv[d];
        int p = atomicAdd(&g_cur[d], 1);
        g_csr[p] = make_int2(s, __float_as_int(w));
    }
}

// ---------------- dense input layer: h = relu(x @ W0 + b0), x:[n,3] ----------------
__global__ void k_input(const float* __restrict__ x, const float* __restrict__ W0,
                        const float* __restrict__ b0, int n) {
    __shared__ float sw[96];
    __shared__ float sb[32];
    int tid = threadIdx.x;
    if (tid < 96) sw[tid] = W0[tid];
    if (tid < 32) sb[tid] = b0[tid];
    __syncthreads();
    int i = blockIdx.x * blockDim.x + tid;
    if (i < n * 32) {
        int node = i >> 5, f = i & 31;
        float x0 = x[node * 3 + 0];
        float x1 = x[node * 3 + 1];
        float x2 = x[node * 3 + 2];
        float o = sb[f] + x0 * sw[f] + x1 * sw[32 + f] + x2 * sw[64 + f];
        g_h[i] = fmaxf(o, 0.f);
    }
}

// ---------------- sparse propagation: g_t[d] = sum_e w_e * in[src_e] ----------------
// warp per dst row, lane = feature
__global__ void k_prop(int in_id, int n) {
    const float* __restrict__ xin = fbuf(in_id);
    int w = (blockIdx.x * blockDim.x + threadIdx.x) >> 5;
    int lane = threadIdx.x & 31;
    if (w >= n) return;
    int s = g_off[w], e = g_off[w + 1];
    float acc = 0.f;
    for (int i = s; i < e; i++) {
        int2 sw = g_csr[i];                                    // uniform within warp
        acc += __int_as_float(sw.y) * xin[sw.x * 32 + lane];   // coalesced 128B gather
    }
    g_t[w * 32 + lane] = acc;
}

// ---- fused: P = prop(T1=g_t's producer input lives in g_t already as T1) ----
// Here: T1 rows are in g_t; this kernel does the SECOND prop (on T1) inline,
// forms T2 = 2*prop(T1) - T0, and computes out = relu(T0 W0 + T1 W1 + T2 W2 + b [+ resid])
__global__ void k_comb(int t0_id, int resid_id, int out_id,
                       const float* __restrict__ Wc, const float* __restrict__ bc, int n) {
    __shared__ float sW[3072];        // [3][32][32]
    __shared__ float sb[32];
    __shared__ float srow[8][3][32];  // per-warp staging of T0/T1/T2 rows
    const float* __restrict__ t0buf = fbuf(t0_id);
    const float* __restrict__ t1buf = g_t;
    float* __restrict__ out = fbuf(out_id);
    int tid = threadIdx.x;
    for (int i = tid; i < 3072; i += blockDim.x) sW[i] = Wc[i];
    if (tid < 32) sb[tid] = bc[tid];
    __syncthreads();

    int node = (blockIdx.x * blockDim.x + tid) >> 5;
    int lane = tid & 31;
    int wi = tid >> 5;
    if (node >= n) return;   // warp-uniform; no block-wide syncs below

    int s = g_off[node], e = g_off[node + 1];
    float acc = 0.f;
    for (int i = s; i < e; i++) {
        int2 sw = g_csr[i];
        acc += __int_as_float(sw.y) * t1buf[sw.x * 32 + lane];
    }
    float t0 = t0buf[node * 32 + lane];
    float t1 = t1buf[node * 32 + lane];
    float t2 = 2.f * acc - t0;

    srow[wi][0][lane] = t0;
    srow[wi][1][lane] = t1;
    srow[wi][2][lane] = t2;
    __syncwarp();

    float o = sb[lane];
#pragma unroll
    for (int i = 0; i < 32; i++) {
        o += srow[wi][0][i] * sW[i * 32 + lane];
        o += srow[wi][1][i] * sW[1024 + i * 32 + lane];
        o += srow[wi][2][i] * sW[2048 + i * 32 + lane];
    }
    if (resid_id >= 0) o += fbuf(resid_id)[node * 32 + lane];
    out[node * 32 + lane] = fmaxf(o, 0.f);
}

// ---------------- output layer: out[n] = g_h[n] . W1 + b1 ----------------
__global__ void k_final(const float* __restrict__ W1, const float* __restrict__ b1,
                        float* __restrict__ out, int n) {
    int node = (blockIdx.x * blockDim.x + threadIdx.x) >> 5;
    int lane = threadIdx.x & 31;
    if (node >= n) return;
    float v = g_h[node * 32 + lane] * W1[lane];
#pragma unroll
    for (int o = 16; o > 0; o >>= 1) v += __shfl_xor_sync(0xffffffffu, v, o);
    if (lane == 0) out[node] = v + b1[0];
}

// ---------------- launch ----------------
extern "C" void kernel_launch(void* const* d_in, const int* in_sizes, int n_in,
                              void* d_out, int out_size) {
    const float* x    = (const float*)d_in[0];
    const void*  ei   = d_in[1];                    // int32 or int64, detected on device
    const float* W0   = (const float*)d_in[2];
    const float* b0   = (const float*)d_in[3];
    const float* c11W = (const float*)d_in[4];
    const float* c11b = (const float*)d_in[5];
    const float* c12W = (const float*)d_in[6];
    const float* c12b = (const float*)d_in[7];
    const float* c21W = (const float*)d_in[8];
    const float* c21b = (const float*)d_in[9];
    const float* c22W = (const float*)d_in[10];
    const float* c22b = (const float*)d_in[11];
    const float* W1   = (const float*)d_in[12];
    const float* b1   = (const float*)d_in[13];
    float* out = (float*)d_out;

    int n = in_sizes[0] / 3;
    int e = in_sizes[1] / 2;
    if (n > NN) n = NN;
    if (e > EE) e = EE;

    const int B = 256;
    int gN  = (n + B - 1) / B;
    int gE  = (e + B - 1) / B;
    int gNF = (n * 32 + B - 1) / B;
    int nb  = (n + 1023) / 1024;

    // graph normalization + CSR build (once per launch)
    k_detect<<<1, 256>>>(ei);
    k_zero<<<gN, B>>>(n);
    k_count<<<gE, B>>>(ei, e);
    k_dinv<<<gN, B>>>(n);
    k_scan1<<<nb, 1024>>>(n);
    k_scan2<<<1, 32>>>(nb, n);
    k_scan3<<<gN, B>>>(n);
    k_scatter<<<gE, B>>>(ei, e);

    // input MLP -> g_h (id 0)
    k_input<<<gNF, B>>>(x, W0, b0, n);

    // buffer ids: 0=g_h, 1=g_a, 2=g_t, 3=g_b
    // block 1
    k_prop<<<gNF, B>>>(0, n);                    // g_t = L~ h
    k_comb<<<gNF, B>>>(0, -1, 1, c11W, c11b, n); // a = relu(conv11(h))
    k_prop<<<gNF, B>>>(1, n);
    k_comb<<<gNF, B>>>(1, 0, 3, c12W, c12b, n);  // b = relu(conv12(a) + h)

    // block 2
    k_prop<<<gNF, B>>>(3, n);
    k_comb<<<gNF, B>>>(3, -1, 1, c21W, c21b, n); // a = relu(conv21(b))
    k_prop<<<gNF, B>>>(1, n);
    k_comb<<<gNF, B>>>(1, 3, 0, c22W, c22b, n);  // h = relu(conv22(a) + b)

    // output layer
    k_final<<<gNF, B>>>(W1, b1, out, n);
}

// round 3
// speedup vs baseline: 1.0082x; 1.0082x over previous
#include <cuda_runtime.h>
#include <cuda_fp16.h>

#define NN 200000
#define EE 3200000

// ---------------- static device scratch ----------------
__device__ int     g_deg[NN];
__device__ int     g_cnt[NN];
__device__ float   g_dinv[NN];
__device__ int     g_off[NN + 1];
__device__ int     g_cur[NN];
__device__ int     g_bsum[1024];
__device__ int     g_is64;
__device__ int     g_src[EE];          // CSR: src only (weight folded into dinv scaling)
__device__ float   g_h[NN * 32];       // fp32 feature buffers
__device__ float   g_a[NN * 32];
__device__ float   g_t[NN * 32];
__device__ float   g_b[NN * 32];
__device__ __half2 s_h[NN * 16];       // fp16 shadows, pre-scaled by dinv[node]
__device__ __half2 s_a[NN * 16];
__device__ __half2 s_t[NN * 16];
__device__ __half2 s_b[NN * 16];

__device__ __forceinline__ float* fbuf(int id) {
    switch (id) { case 0: return g_h; case 1: return g_a; case 2: return g_t; default: return g_b; }
}
__device__ __forceinline__ __half2* hbuf(int id) {
    switch (id) { case 0: return s_h; case 1: return s_a; case 2: return s_t; default: return s_b; }
}

__device__ __forceinline__ int edge_at(const void* ei, int idx, int is64) {
    if (is64) return (int)((const long long*)ei)[idx];
    return ((const int*)ei)[idx];
}

// ---------------- setup ----------------
__global__ void k_detect(const void* ei) {
    __shared__ int any;
    if (threadIdx.x == 0) any = 0;
    __syncthreads();
    const int* w = (const int*)ei;
    for (int i = threadIdx.x; i < 1024; i += blockDim.x)
        if (w[2 * i + 1] != 0) atomicOr(&any, 1);
    __syncthreads();
    if (threadIdx.x == 0) g_is64 = (any == 0) ? 1 : 0;
}

__global__ void k_zero(int n) {
    int i = blockIdx.x * blockDim.x + threadIdx.x;
    if (i < n) { g_deg[i] = 0; g_cnt[i] = 0; }
}

__global__ void k_count(const void* ei, int e) {
    int i = blockIdx.x * blockDim.x + threadIdx.x;
    if (i < e) {
        int is64 = g_is64;
        int s = edge_at(ei, i, is64);
        int d = edge_at(ei, e + i, is64);
        atomicAdd(&g_deg[s], 1);
        atomicAdd(&g_cnt[d], 1);
    }
}

__global__ void k_dinv(int n) {
    int i = blockIdx.x * blockDim.x + threadIdx.x;
    if (i < n) {
        int d = g_deg[i];
        g_dinv[i] = (d > 0) ? rsqrtf((float)d) : 0.f;
    }
}

__global__ void k_scan1(int n) {
    __shared__ int sh[1024];
    int tid = threadIdx.x;
    int i = blockIdx.x * 1024 + tid;
    int v = (i < n) ? g_cnt[i] : 0;
    sh[tid] = v;
    __syncthreads();
    for (int d = 1; d < 1024; d <<= 1) {
        int t = (tid >= d) ? sh[tid - d] : 0;
        __syncthreads();
        sh[tid] += t;
        __syncthreads();
    }
    if (i < n) g_off[i] = sh[tid] - v;
    if (tid == 1023) g_bsum[blockIdx.x] = sh[1023];
}

__global__ void k_scan2(int nb, int n) {
    if (threadIdx.x == 0 && blockIdx.x == 0) {
        int a = 0;
        for (int b = 0; b < nb; b++) { int t = g_bsum[b]; g_bsum[b] = a; a += t; }
        g_off[n] = a;
    }
}

__global__ void k_scan3(int n) {
    int i = blockIdx.x * blockDim.x + threadIdx.x;
    if (i < n) {
        int o = g_off[i] + g_bsum[i >> 10];
        g_off[i] = o;
        g_cur[i] = o;
    }
}

__global__ void k_scatter(const void* ei, int e) {
    int i = blockIdx.x * blockDim.x + threadIdx.x;
    if (i < e) {
        int is64 = g_is64;
        int s = edge_at(ei, i, is64);
        int d = edge_at(ei, e + i, is64);
        int p = atomicAdd(&g_cur[d], 1);
        g_src[p] = s;
    }
}

// ---------------- input layer: h = relu(x @ W0 + b0) + fp16 shadow ----------------
__global__ void k_input(const float* __restrict__ x, const float* __restrict__ W0,
                        const float* __restrict__ b0, int n) {
    __shared__ float sw[96];
    __shared__ float sb[32];
    int tid = threadIdx.x;
    if (tid < 96) sw[tid] = W0[tid];
    if (tid < 32) sb[tid] = b0[tid];
    __syncthreads();
    int i = blockIdx.x * blockDim.x + tid;
    if (i < n * 32) {
        int node = i >> 5, f = i & 31;
        float x0 = x[node * 3 + 0];
        float x1 = x[node * 3 + 1];
        float x2 = x[node * 3 + 2];
        float o = sb[f] + x0 * sw[f] + x1 * sw[32 + f] + x2 * sw[64 + f];
        o = fmaxf(o, 0.f);
        g_h[i] = o;
        // shadow (pre-scaled by dinv): pair lanes into half2
        float di = g_dinv[node];
        float o_hi = __shfl_down_sync(0xffffffffu, o, 1);
        if ((f & 1) == 0)
            s_h[node * 16 + (f >> 1)] = __floats2half2_rn(di * o, di * o_hi);
    }
}

// ---------------- prop: T1 = L~ x ; half-warp per dst row ----------------
__global__ void k_prop(int in_id, int n) {
    const __half2* __restrict__ xh = hbuf(in_id);
    int t = blockIdx.x * blockDim.x + threadIdx.x;
    int row = t >> 4;
    int hl = t & 15;
    if (row >= n) return;
    int s = g_off[row], e = g_off[row + 1];
    float2 acc = make_float2(0.f, 0.f);
#pragma unroll 4
    for (int i = s; i < e; i++) {
        int src = __ldg(&g_src[i]);
        float2 f = __half22float2(xh[src * 16 + hl]);
        acc.x += f.x; acc.y += f.y;
    }
    float di = g_dinv[row];
    float2 r = make_float2(-di * acc.x, -di * acc.y);
    ((float2*)g_t)[row * 16 + hl] = r;
    s_t[row * 16 + hl] = __floats2half2_rn(di * r.x, di * r.y);
}

// ---------------- fused second prop + Chebyshev combine ----------------
// T1 in g_t/s_t; computes P=prop(T1), T2=2P-T0, out=relu(T0 W0 + T1 W1 + T2 W2 + b [+resid])
__global__ void k_comb(int t0_id, int resid_id, int out_id,
                       const float* __restrict__ Wc, const float* __restrict__ bc, int n) {
    __shared__ float sW[3072];
    __shared__ float sb[32];
    __shared__ float srow[8][3][32];
    const float* __restrict__ t0f = fbuf(t0_id);
    float* __restrict__ outf = fbuf(out_id);
    __half2* __restrict__ outsh = hbuf(out_id);
    int tid = threadIdx.x;
    for (int i = tid; i < 3072; i += blockDim.x) sW[i] = Wc[i];
    if (tid < 32) sb[tid] = bc[tid];
    __syncthreads();

    int node = (blockIdx.x * blockDim.x + tid) >> 5;
    int lane = tid & 31;
    int wi = tid >> 5;
    if (node >= n) return;          // warp-uniform

    float di = g_dinv[node];
    int hl = lane & 15;
    if (lane < 16) {
        int s = g_off[node], e = g_off[node + 1];
        float2 acc = make_float2(0.f, 0.f);
#pragma unroll 4
        for (int i = s; i < e; i++) {
            int src = __ldg(&g_src[i]);
            float2 f = __half22float2(s_t[src * 16 + hl]);
            acc.x += f.x; acc.y += f.y;
        }
        float2 t0v = ((const float2*)t0f)[node * 16 + hl];
        // T2 = 2*(-di*acc) - T0
        srow[wi][2][2 * hl]     = fmaf(-2.f * di, acc.x, -t0v.x);
        srow[wi][2][2 * hl + 1] = fmaf(-2.f * di, acc.y, -t0v.y);
    }
    srow[wi][0][lane] = t0f[node * 32 + lane];
    srow[wi][1][lane] = g_t[node * 32 + lane];
    __syncwarp();

    float o = sb[lane];
#pragma unroll
    for (int i = 0; i < 32; i++) {
        o += srow[wi][0][i] * sW[i * 32 + lane];
        o += srow[wi][1][i] * sW[1024 + i * 32 + lane];
        o += srow[wi][2][i] * sW[2048 + i * 32 + lane];
    }
    if (resid_id >= 0) o += fbuf(resid_id)[node * 32 + lane];
    o = fmaxf(o, 0.f);
    outf[node * 32 + lane] = o;
    float o_hi = __shfl_down_sync(0xffffffffu, o, 1);
    if ((lane & 1) == 0)
        outsh[node * 16 + (lane >> 1)] = __floats2half2_rn(di * o, di * o_hi);
}

// ---------------- output layer ----------------
__global__ void k_final(const float* __restrict__ W1, const float* __restrict__ b1,
                        float* __restrict__ out, int n) {
    int node = (blockIdx.x * blockDim.x + threadIdx.x) >> 5;
    int lane = threadIdx.x & 31;
    if (node >= n) return;
    float v = g_h[node * 32 + lane] * W1[lane];
#pragma unroll
    for (int o = 16; o > 0; o >>= 1) v += __shfl_xor_sync(0xffffffffu, v, o);
    if (lane == 0) out[node] = v + b1[0];
}

// ---------------- launch ----------------
extern "C" void kernel_launch(void* const* d_in, const int* in_sizes, int n_in,
                              void* d_out, int out_size) {
    const float* x    = (const float*)d_in[0];
    const void*  ei   = d_in[1];
    const float* W0   = (const float*)d_in[2];
    const float* b0   = (const float*)d_in[3];
    const float* c11W = (const float*)d_in[4];
    const float* c11b = (const float*)d_in[5];
    const float* c12W = (const float*)d_in[6];
    const float* c12b = (const float*)d_in[7];
    const float* c21W = (const float*)d_in[8];
    const float* c21b = (const float*)d_in[9];
    const float* c22W = (const float*)d_in[10];
    const float* c22b = (const float*)d_in[11];
    const float* W1   = (const float*)d_in[12];
    const float* b1   = (const float*)d_in[13];
    float* out = (float*)d_out;

    int n = in_sizes[0] / 3;
    int e = in_sizes[1] / 2;
    if (n > NN) n = NN;
    if (e > EE) e = EE;

    const int B = 256;
    int gN  = (n + B - 1) / B;
    int gE  = (e + B - 1) / B;
    int gNF = (n * 32 + B - 1) / B;     // 32 threads per node
    int gNP = (n * 16 + B - 1) / B;     // 16 threads per node (prop)
    int nb  = (n + 1023) / 1024;

    // CSR build
    k_detect<<<1, 256>>>(ei);
    k_zero<<<gN, B>>>(n);
    k_count<<<gE, B>>>(ei, e);
    k_dinv<<<gN, B>>>(n);
    k_scan1<<<nb, 1024>>>(n);
    k_scan2<<<1, 32>>>(nb, n);
    k_scan3<<<gN, B>>>(n);
    k_scatter<<<gE, B>>>(ei, e);

    // input MLP -> buffers id 0 (g_h/s_h)
    k_input<<<gNF, B>>>(x, W0, b0, n);

    // ids: 0=h, 1=a, 2=t, 3=b
    // block 1
    k_prop<<<gNP, B>>>(0, n);
    k_comb<<<gNF, B>>>(0, -1, 1, c11W, c11b, n);
    k_prop<<<gNP, B>>>(1, n);
    k_comb<<<gNF, B>>>(1, 0, 3, c12W, c12b, n);
    // block 2
    k_prop<<<gNP, B>>>(3, n);
    k_comb<<<gNF, B>>>(3, -1, 1, c21W, c21b, n);
    k_prop<<<gNP, B>>>(1, n);
    k_comb<<<gNF, B>>>(1, 3, 0, c22W, c22b, n);

    k_final<<<gNF, B>>>(W1, b1, out, n);
}

// round 4
// speedup vs baseline: 1.2901x; 1.2797x over previous
#include <cuda_runtime.h>
#include <cuda_fp16.h>

#define NN 200000
#define EE 3200000

// ---------------- static device scratch ----------------
__device__ int     g_deg[NN];
__device__ int     g_cnt[NN];
__device__ float   g_dinv[NN];
__device__ int     g_off[NN + 1];
__device__ int     g_cur[NN];
__device__ int     g_bsum[1024];
__device__ int     g_is64;
__device__ int     g_src[EE];          // CSR src (weights folded into dinv scaling)
__device__ float   g_h[NN * 32];       // fp32 feature buffers
__device__ float   g_a[NN * 32];
__device__ float   g_t[NN * 32];
__device__ float   g_b[NN * 32];
__device__ __half2 s_h[NN * 16];       // fp16 shadows, pre-scaled by dinv[node]
__device__ __half2 s_a[NN * 16];
__device__ __half2 s_t[NN * 16];
__device__ __half2 s_b[NN * 16];

__device__ __forceinline__ float* fbuf(int id) {
    switch (id) { case 0: return g_h; case 1: return g_a; case 2: return g_t; default: return g_b; }
}
__device__ __forceinline__ __half2* hbuf(int id) {
    switch (id) { case 0: return s_h; case 1: return s_a; case 2: return s_t; default: return s_b; }
}

__device__ __forceinline__ int edge_at(const void* ei, int idx, int is64) {
    if (is64) return (int)((const long long*)ei)[idx];
    return ((const int*)ei)[idx];
}

// ---------------- setup ----------------
__global__ void k_detect(const void* ei) {
    __shared__ int any;
    if (threadIdx.x == 0) any = 0;
    __syncthreads();
    const int* w = (const int*)ei;
    for (int i = threadIdx.x; i < 1024; i += blockDim.x)
        if (w[2 * i + 1] != 0) atomicOr(&any, 1);
    __syncthreads();
    if (threadIdx.x == 0) g_is64 = (any == 0) ? 1 : 0;
}

__global__ void k_zero(int n) {
    int i = blockIdx.x * blockDim.x + threadIdx.x;
    if (i < n) { g_deg[i] = 0; g_cnt[i] = 0; }
}

__global__ void k_count(const void* ei, int e) {
    int i = blockIdx.x * blockDim.x + threadIdx.x;
    if (i < e) {
        int is64 = g_is64;
        int s = edge_at(ei, i, is64);
        int d = edge_at(ei, e + i, is64);
        atomicAdd(&g_deg[s], 1);
        atomicAdd(&g_cnt[d], 1);
    }
}

__global__ void k_dinv(int n) {
    int i = blockIdx.x * blockDim.x + threadIdx.x;
    if (i < n) {
        int d = g_deg[i];
        g_dinv[i] = (d > 0) ? rsqrtf((float)d) : 0.f;
    }
}

__global__ void k_scan1(int n) {
    __shared__ int sh[1024];
    int tid = threadIdx.x;
    int i = blockIdx.x * 1024 + tid;
    int v = (i < n) ? g_cnt[i] : 0;
    sh[tid] = v;
    __syncthreads();
    for (int d = 1; d < 1024; d <<= 1) {
        int t = (tid >= d) ? sh[tid - d] : 0;
        __syncthreads();
        sh[tid] += t;
        __syncthreads();
    }
    if (i < n) g_off[i] = sh[tid] - v;
    if (tid == 1023) g_bsum[blockIdx.x] = sh[1023];
}

__global__ void k_scan2(int nb, int n) {
    if (threadIdx.x == 0 && blockIdx.x == 0) {
        int a = 0;
        for (int b = 0; b < nb; b++) { int t = g_bsum[b]; g_bsum[b] = a; a += t; }
        g_off[n] = a;
    }
}

__global__ void k_scan3(int n) {
    int i = blockIdx.x * blockDim.x + threadIdx.x;
    if (i < n) {
        int o = g_off[i] + g_bsum[i >> 10];
        g_off[i] = o;
        g_cur[i] = o;
    }
}

__global__ void k_scatter(const void* ei, int e) {
    int i = blockIdx.x * blockDim.x + threadIdx.x;
    if (i < e) {
        int is64 = g_is64;
        int s = edge_at(ei, i, is64);
        int d = edge_at(ei, e + i, is64);
        int p = atomicAdd(&g_cur[d], 1);
        g_src[p] = s;
    }
}

// ---------------- input layer: h = relu(x @ W0 + b0) + fp16 shadow ----------------
__global__ void k_input(const float* __restrict__ x, const float* __restrict__ W0,
                        const float* __restrict__ b0, int n) {
    __shared__ float sw[96];
    __shared__ float sb[32];
    int tid = threadIdx.x;
    if (tid < 96) sw[tid] = W0[tid];
    if (tid < 32) sb[tid] = b0[tid];
    __syncthreads();
    int i = blockIdx.x * blockDim.x + tid;
    if (i < n * 32) {
        int node = i >> 5, f = i & 31;
        float x0 = x[node * 3 + 0];
        float x1 = x[node * 3 + 1];
        float x2 = x[node * 3 + 2];
        float o = sb[f] + x0 * sw[f] + x1 * sw[32 + f] + x2 * sw[64 + f];
        o = fmaxf(o, 0.f);
        g_h[i] = o;
        float di = g_dinv[node];
        float o_hi = __shfl_down_sync(0xffffffffu, o, 1);
        if ((f & 1) == 0)
            s_h[node * 16 + (f >> 1)] = __floats2half2_rn(di * o, di * o_hi);
    }
}

// -------- warp gather: 4 edges/iter, 8 lanes x 8B per edge; returns full row sum in all lanes --------
__device__ __forceinline__ float4 gather4(const uint2* __restrict__ sh, int s, int e, int g, int c) {
    float4 acc = make_float4(0.f, 0.f, 0.f, 0.f);
#pragma unroll 2
    for (int i = s + g; i < e; i += 4) {
        int src = __ldg(&g_src[i]);
        uint2 v = __ldg(&sh[src * 8 + c]);
        float2 f0 = __half22float2(*reinterpret_cast<__half2*>(&v.x));
        float2 f1 = __half22float2(*reinterpret_cast<__half2*>(&v.y));
        acc.x += f0.x; acc.y += f0.y; acc.z += f1.x; acc.w += f1.y;
    }
#pragma unroll
    for (int o = 8; o <= 16; o <<= 1) {
        acc.x += __shfl_xor_sync(0xffffffffu, acc.x, o);
        acc.y += __shfl_xor_sync(0xffffffffu, acc.y, o);
        acc.z += __shfl_xor_sync(0xffffffffu, acc.z, o);
        acc.w += __shfl_xor_sync(0xffffffffu, acc.w, o);
    }
    return acc;
}

// ---------------- prop: T1 = L~ x ; warp per row ----------------
__global__ void k_prop(int in_id, int n) {
    const uint2* __restrict__ xh = (const uint2*)hbuf(in_id);
    int w = (blockIdx.x * blockDim.x + threadIdx.x) >> 5;
    int lane = threadIdx.x & 31;
    if (w >= n) return;
    int g = lane >> 3, c = lane & 7;
    int s = g_off[w], e = g_off[w + 1];
    float4 acc = gather4(xh, s, e, g, c);
    float di = g_dinv[w];
    if (g == 0) {
        float4 r = make_float4(-di * acc.x, -di * acc.y, -di * acc.z, -di * acc.w);
        ((float4*)g_t)[w * 8 + c] = r;
        __half2 ha = __floats2half2_rn(di * r.x, di * r.y);
        __half2 hb = __floats2half2_rn(di * r.z, di * r.w);
        uint2 o;
        o.x = *reinterpret_cast<unsigned*>(&ha);
        o.y = *reinterpret_cast<unsigned*>(&hb);
        ((uint2*)s_t)[w * 8 + c] = o;
    }
}

// ---------------- fused second prop + tiled Chebyshev combine ----------------
// tile = 32 nodes per block (256 threads, 8 warps x 4 nodes in gather phase)
__global__ void __launch_bounds__(256) k_comb(int t0_id, int resid_id, int out_id,
                       const float* __restrict__ Wc, const float* __restrict__ bc, int n) {
    __shared__ float sT[32][100];   // concat [t0|t1|t2] per node, pad to 100
    __shared__ float sWt[32][100];  // Wt[f][k], k = 0..95
    __shared__ float sO[32][33];    // staged outputs
    const float* __restrict__ t0f = fbuf(t0_id);
    float* __restrict__ outf = fbuf(out_id);
    uint2* __restrict__ outsh = (uint2*)hbuf(out_id);

    int tid = threadIdx.x;
    int wid = tid >> 5, lane = tid & 31;
    int g = lane >> 3, c = lane & 7;
    int base = blockIdx.x << 5;

    // stage transposed weights: sWt[f][k] = Wc[k*32+f]
#pragma unroll
    for (int rep = 0; rep < 12; rep++) {
        int idx = rep * 256 + tid;
        sWt[idx & 31][idx >> 5] = Wc[idx];
    }

    // gather phase: warp w handles nodes base + w*4 + j
#pragma unroll
    for (int j = 0; j < 4; j++) {
        int nl = (wid << 2) + j;
        int node = base + nl;
        if (node < n) {
            int s = g_off[node], e = g_off[node + 1];
            float4 acc = gather4((const uint2*)s_t, s, e, g, c);
            if (g == 0) {
                float di = g_dinv[node];
                float4 t0v = ((const float4*)t0f)[node * 8 + c];
                float4 t1v = ((const float4*)g_t)[node * 8 + c];
                float4 t2v;
                t2v.x = fmaf(-2.f * di, acc.x, -t0v.x);
                t2v.y = fmaf(-2.f * di, acc.y, -t0v.y);
                t2v.z = fmaf(-2.f * di, acc.z, -t0v.z);
                t2v.w = fmaf(-2.f * di, acc.w, -t0v.w);
                *(float4*)&sT[nl][c * 4]      = t0v;
                *(float4*)&sT[nl][32 + c * 4] = t1v;
                *(float4*)&sT[nl][64 + c * 4] = t2v;
            }
        }
    }
    __syncthreads();

    // dense phase: warp wid computes features {wid, wid+8, wid+16, wid+24} for node = lane
    {
        float acc0 = __ldg(&bc[wid]);
        float acc1 = __ldg(&bc[wid + 8]);
        float acc2 = __ldg(&bc[wid + 16]);
        float acc3 = __ldg(&bc[wid + 24]);
#pragma unroll
        for (int kc = 0; kc < 24; kc++) {
            float4 t = *(const float4*)&sT[lane][kc * 4];
            float4 w0 = *(const float4*)&sWt[wid][kc * 4];
            float4 w1 = *(const float4*)&sWt[wid + 8][kc * 4];
            float4 w2 = *(const float4*)&sWt[wid + 16][kc * 4];
            float4 w3 = *(const float4*)&sWt[wid + 24][kc * 4];
            acc0 += t.x * w0.x + t.y * w0.y + t.z * w0.z + t.w * w0.w;
            acc1 += t.x * w1.x + t.y * w1.y + t.z * w1.z + t.w * w1.w;
            acc2 += t.x * w2.x + t.y * w2.y + t.z * w2.z + t.w * w2.w;
            acc3 += t.x * w3.x + t.y * w3.y + t.z * w3.z + t.w * w3.w;
        }
        sO[lane][wid]      = acc0;
        sO[lane][wid + 8]  = acc1;
        sO[lane][wid + 16] = acc2;
        sO[lane][wid + 24] = acc3;
    }
    __syncthreads();

    // epilogue: 256 threads -> 32 nodes x 8 chunks; resid + relu + fp32/fp16 stores
    {
        int nl = tid >> 3, cc = tid & 7;
        int node = base + nl;
        if (node < n) {
            float4 o;
            o.x = sO[nl][cc * 4 + 0];
            o.y = sO[nl][cc * 4 + 1];
            o.z = sO[nl][cc * 4 + 2];
            o.w = sO[nl][cc * 4 + 3];
            if (resid_id >= 0) {
                float4 rv = ((const float4*)fbuf(resid_id))[node * 8 + cc];
                o.x += rv.x; o.y += rv.y; o.z += rv.z; o.w += rv.w;
            }
            o.x = fmaxf(o.x, 0.f); o.y = fmaxf(o.y, 0.f);
            o.z = fmaxf(o.z, 0.f); o.w = fmaxf(o.w, 0.f);
            ((float4*)outf)[node * 8 + cc] = o;
            float di = g_dinv[node];
            __half2 ha = __floats2half2_rn(di * o.x, di * o.y);
            __half2 hb = __floats2half2_rn(di * o.z, di * o.w);
            uint2 sh;
            sh.x = *reinterpret_cast<unsigned*>(&ha);
            sh.y = *reinterpret_cast<unsigned*>(&hb);
            outsh[node * 8 + cc] = sh;
        }
    }
}

// ---------------- output layer ----------------
__global__ void k_final(const float* __restrict__ W1, const float* __restrict__ b1,
                        float* __restrict__ out, int n) {
    int node = (blockIdx.x * blockDim.x + threadIdx.x) >> 5;
    int lane = threadIdx.x & 31;
    if (node >= n) return;
    float v = g_h[node * 32 + lane] * W1[lane];
#pragma unroll
    for (int o = 16; o > 0; o >>= 1) v += __shfl_xor_sync(0xffffffffu, v, o);
    if (lane == 0) out[node] = v + b1[0];
}

// ---------------- launch ----------------
extern "C" void kernel_launch(void* const* d_in, const int* in_sizes, int n_in,
                              void* d_out, int out_size) {
    const float* x    = (const float*)d_in[0];
    const void*  ei   = d_in[1];
    const float* W0   = (const float*)d_in[2];
    const float* b0   = (const float*)d_in[3];
    const float* c11W = (const float*)d_in[4];
    const float* c11b = (const float*)d_in[5];
    const float* c12W = (const float*)d_in[6];
    const float* c12b = (const float*)d_in[7];
    const float* c21W = (const float*)d_in[8];
    const float* c21b = (const float*)d_in[9];
    const float* c22W = (const float*)d_in[10];
    const float* c22b = (const float*)d_in[11];
    const float* W1   = (const float*)d_in[12];
    const float* b1   = (const float*)d_in[13];
    float* out = (float*)d_out;

    int n = in_sizes[0] / 3;
    int e = in_sizes[1] / 2;
    if (n > NN) n = NN;
    if (e > EE) e = EE;

    const int B = 256;
    int gN  = (n + B - 1) / B;
    int gE  = (e + B - 1) / B;
    int gNF = (n * 32 + B - 1) / B;       // 32 threads/node
    int gW  = (n * 32 + B - 1) / B;       // warp per row (prop)
    int gT  = (n + 31) / 32;              // 32-node tiles (comb)
    int nb  = (n + 1023) / 1024;

    // CSR build
    k_detect<<<1, 256>>>(ei);
    k_zero<<<gN, B>>>(n);
    k_count<<<gE, B>>>(ei, e);
    k_dinv<<<gN, B>>>(n);
    k_scan1<<<nb, 1024>>>(n);
    k_scan2<<<1, 32>>>(nb, n);
    k_scan3<<<gN, B>>>(n);
    k_scatter<<<gE, B>>>(ei, e);

    // input MLP -> id 0 (g_h/s_h)
    k_input<<<gNF, B>>>(x, W0, b0, n);

    // ids: 0=h, 1=a, 2=t, 3=b
    k_prop<<<gW, B>>>(0, n);
    k_comb<<<gT, B>>>(0, -1, 1, c11W, c11b, n);
    k_prop<<<gW, B>>>(1, n);
    k_comb<<<gT, B>>>(1, 0, 3, c12W, c12b, n);
    k_prop<<<gW, B>>>(3, n);
    k_comb<<<gT, B>>>(3, -1, 1, c21W, c21b, n);
    k_prop<<<gW, B>>>(1, n);
    k_comb<<<gT, B>>>(1, 3, 0, c22W, c22b, n);

    k_final<<<gNF, B>>>(W1, b1, out, n);
}